// round 13
// baseline (speedup 1.0000x reference)
#include <cuda_runtime.h>

// MDN_module — sector-table kernel, single-LDS sector lookup.
// b1 == 0 => hinges through origin => MLP piecewise-linear over <=128 angular
// sectors: f_k(x) = b2_k + A_s[k][0]*x0 + A_s[k][1]*x1.
// Lookup: diamond pseudo-angle -> 1024-entry bucket table where pure buckets
// store the sector id directly (one dependent LDS); impure buckets fall back
// to a short sorted-boundary walk. sA packed as u64 pairs, stride 5.
// Uniform fallback path handles b1 != 0 (never taken on this dataset).
// Inputs: x[B,2] y[B,1,2] eps[B,1,2] W1[2,64] b1[64] W2[64,4] b2[4] Wv[2,2]
// Output: fx (2B floats) then logp_y scalar at out[2B].

typedef unsigned long long u64;

#define NT 512
#define MAXBLK 2048
#define NBUCKET 1024

__device__ double g_part[MAXBLK];
__device__ unsigned g_ticket = 0;

__device__ __forceinline__ float pangle(float x0, float x1) {
    float t = __fdividef(x1, fabsf(x0) + fabsf(x1));
    return (x0 >= 0.0f) ? t : 2.0f - t;
}
__device__ __forceinline__ u64 pk2(float lo, float hi) {
    u64 r; asm("mov.b64 %0, {%1, %2};" : "=l"(r) : "f"(lo), "f"(hi)); return r;
}
__device__ __forceinline__ void upk2(float& lo, float& hi, u64 v) {
    asm("mov.b64 {%0, %1}, %2;" : "=f"(lo), "=f"(hi) : "l"(v));
}

// per-row epilogue: returns d0^2/v0 + d1^2/v1 + f2 + f3 ; writes fx0,fx1
__device__ __forceinline__ float row_tail(
    float x0, float x1, float mu0, float mu1, float f2, float f3,
    float y0, float y1, float e0, float e1,
    float wv00, float wv01, float wv10, float wv11,
    float& fx0, float& fx1)
{
    float z0 = fmaf(x0, wv00, x1 * wv10);
    float z1 = fmaf(x0, wv01, x1 * wv11);
    float Vx = fmaf(z0, z0, fmaf(z1, z1, 1e-3f));
    float m0 = fmaf(mu0, wv00, mu1 * wv10);
    float m1 = fmaf(mu0, wv01, mu1 * wv11);
    float Vmu = fmaf(m0, m0, fmaf(m1, m1, 1e-3f));
    float scale = __fdividef(fminf(0.99f * Vx, Vmu), Vmu);  // == beta*Vx - relu(...)
    float ms0 = mu0 * scale;
    float ms1 = mu1 * scale;
    float v0 = __expf(f2);
    float v1 = __expf(f3);
    float r0 = rsqrtf(v0);
    float r1 = rsqrtf(v1);
    fx0 = fmaf(v0 * r0, e0, ms0);
    fx1 = fmaf(v1 * r1, e1, ms1);
    float d0 = y0 - ms0;
    float d1 = y1 - ms1;
    float s = fmaf(d0 * d0, r0 * r0, f2 + f3);   // log v0 + log v1 == f2 + f3 exactly
    s = fmaf(d1 * d1, r1 * r1, s);
    return s;
}

__global__ void __launch_bounds__(NT, 2)
mdn_fused(const float4* __restrict__ x4, const float4* __restrict__ y4,
          const float4* __restrict__ e4,
          const float* __restrict__ W1, const float* __restrict__ b1,
          const float* __restrict__ W2, const float* __restrict__ b2,
          const float* __restrict__ Wv,
          float4* __restrict__ o4, float* __restrict__ out,
          int nPair, long long B)
{
    __shared__ float sBound[129];       // sorted boundary pseudo-angles + INF sentinel
    __shared__ u64 sA64[128 * 5];       // per-sector maps: 4 packed u64 + pad, stride 5
    __shared__ int sBkt[NBUCKET];       // >=0: pure sector id ; <0: -(start count)-1
    __shared__ float sP[128];
    __shared__ float sw0[64], sw1[64];
    __shared__ float sc[64][4];
    __shared__ int sFast;
    __shared__ double swred[NT / 32];

    int t = threadIdx.x;
    if (t == 0) sFast = 1;
    __syncthreads();
    if (t < 64) {
        float w0 = W1[t], w1 = W1[64 + t];
        sw0[t] = w0; sw1[t] = w1;
#pragma unroll
        for (int k = 0; k < 4; k++) sc[t][k] = W2[t * 4 + k];
        float pa = pangle(-w1, w0);     // hinge-line directions (perp to w)
        float pb = pangle(w1, -w0);
        if (!(pa == pa)) pa = -1.0f;    // degenerate w==0: harmless duplicate boundary
        if (!(pb == pb)) pb = -1.0f;
        sP[t] = pa; sP[64 + t] = pb;
        if (b1[t] != 0.0f) sFast = 0;   // benign race, all writers write 0
    }
    __syncthreads();
    if (t < 128) {                       // rank sort (ties broken by index)
        float p = sP[t];
        int rank = 0;
        for (int i = 0; i < 128; i++) {
            float pi = sP[i];
            rank += (pi < p) || (pi == p && i < t);
        }
        sBound[rank] = p;
    }
    if (t == 0) sBound[128] = __int_as_float(0x7F800000);   // +INF sentinel
    __syncthreads();
    if (t < 128) {                       // per-sector affine map from midpoint dir
        float p0 = sBound[t];
        float p1 = (t < 127) ? sBound[t + 1] : (sBound[0] + 4.0f);
        float pm = 0.5f * (p0 + p1);
        if (pm >= 3.0f) pm -= 4.0f;
        float u0, u1;                    // inverse diamond map
        if (pm <= 1.0f) { u1 = pm;        u0 = 1.0f - fabsf(pm); }
        else            { u1 = 2.0f - pm; u0 = fabsf(2.0f - pm) - 1.0f; }
        float A[8] = {0, 0, 0, 0, 0, 0, 0, 0};
        for (int j = 0; j < 64; j++) {
            float w0 = sw0[j], w1 = sw1[j];
            float m = (fmaf(u0, w0, u1 * w1) > 0.0f) ? 1.0f : 0.0f;
#pragma unroll
            for (int k = 0; k < 4; k++) {
                float c = sc[j][k] * m;
                A[2 * k]     = fmaf(c, w0, A[2 * k]);
                A[2 * k + 1] = fmaf(c, w1, A[2 * k + 1]);
            }
        }
#pragma unroll
        for (int k = 0; k < 4; k++) sA64[t * 5 + k] = pk2(A[2 * k], A[2 * k + 1]);
        sA64[t * 5 + 4] = 0ull;
    }
    __syncthreads();
    for (int q = t; q < NBUCKET; q += NT) {  // bucket table: pure-sector or walk start
        float e0 = -1.0f + (4.0f / NBUCKET) * (float)q;
        float e1 = -1.0f + (4.0f / NBUCKET) * (float)(q + 1);
        int c0 = 0, c1 = 0;
        for (int i = 0; i < 128; i++) {
            float bi = sBound[i];
            c0 += (bi <= e0) ? 1 : 0;
            c1 += (bi <= e1) ? 1 : 0;
        }
        // boundary exactly at the right edge belongs to the NEXT bucket's count:
        // p in [e0, e1): count(p) in [c0, c1'] where c1' counts bi <= p < e1.
        int c1x = 0;
        for (int i = 0; i < 128; i++) c1x += (sBound[i] < e1) ? 1 : 0;
        if (c0 == c1x) sBkt[q] = (c0 == 0) ? 127 : ((c0 - 1) & 127);
        else           sBkt[q] = -c0 - 1;
    }
    __syncthreads();

    float B20 = b2[0], B21 = b2[1], B22 = b2[2], B23 = b2[3];
    float wv00 = Wv[0], wv01 = Wv[1], wv10 = Wv[2], wv11 = Wv[3];

    float lsum = 0.0f;
    int gtid = blockIdx.x * NT + t;
    int gstride = gridDim.x * NT;

    if (sFast) {
        for (int i = gtid; i < nPair; i += gstride) {
            float4 xv = __ldcs(&x4[i]);
            float4 yv = __ldcs(&y4[i]);
            float4 ev = __ldcs(&e4[i]);

            // two independent lookup chains
            float pa = pangle(xv.x, xv.y);
            float pb = pangle(xv.z, xv.w);
            int qa = min(max((int)((pa + 1.0f) * (NBUCKET / 4.0f)), 0), NBUCKET - 1);
            int qb = min(max((int)((pb + 1.0f) * (NBUCKET / 4.0f)), 0), NBUCKET - 1);
            int ea = sBkt[qa];
            int eb = sBkt[qb];
            int sa, sb;
            if (ea >= 0) sa = ea;
            else {
                int c = -ea - 1;
                while (sBound[c] <= pa) c++;
                sa = (c == 0) ? 127 : c - 1;
            }
            if (eb >= 0) sb = eb;
            else {
                int c = -eb - 1;
                while (sBound[c] <= pb) c++;
                sb = (c == 0) ? 127 : c - 1;
            }

            const u64* Aa = &sA64[sa * 5];
            const u64* Ab = &sA64[sb * 5];
            float Aa0, Aa1, Aa2, Aa3, Aa4, Aa5, Aa6, Aa7;
            float Ab0, Ab1, Ab2, Ab3, Ab4, Ab5, Ab6, Ab7;
            upk2(Aa0, Aa1, Aa[0]); upk2(Aa2, Aa3, Aa[1]);
            upk2(Aa4, Aa5, Aa[2]); upk2(Aa6, Aa7, Aa[3]);
            upk2(Ab0, Ab1, Ab[0]); upk2(Ab2, Ab3, Ab[1]);
            upk2(Ab4, Ab5, Ab[2]); upk2(Ab6, Ab7, Ab[3]);

            float mu0a = fmaf(Aa0, xv.x, fmaf(Aa1, xv.y, B20));
            float mu1a = fmaf(Aa2, xv.x, fmaf(Aa3, xv.y, B21));
            float f2a  = fmaf(Aa4, xv.x, fmaf(Aa5, xv.y, B22));
            float f3a  = fmaf(Aa6, xv.x, fmaf(Aa7, xv.y, B23));
            float mu0b = fmaf(Ab0, xv.z, fmaf(Ab1, xv.w, B20));
            float mu1b = fmaf(Ab2, xv.z, fmaf(Ab3, xv.w, B21));
            float f2b  = fmaf(Ab4, xv.z, fmaf(Ab5, xv.w, B22));
            float f3b  = fmaf(Ab6, xv.z, fmaf(Ab7, xv.w, B23));

            float4 o;
            lsum += row_tail(xv.x, xv.y, mu0a, mu1a, f2a, f3a, yv.x, yv.y, ev.x, ev.y,
                             wv00, wv01, wv10, wv11, o.x, o.y);
            lsum += row_tail(xv.z, xv.w, mu0b, mu1b, f2b, f3b, yv.z, yv.w, ev.z, ev.w,
                             wv00, wv01, wv10, wv11, o.z, o.w);
            __stcs(&o4[i], o);
        }
        // odd tail row (B even here; safety)
        long long start = 2LL * nPair;
        if (blockIdx.x == 0 && start + t < B) {
            long long r = start + t;
            const float* x = (const float*)x4;
            const float* y = (const float*)y4;
            const float* e = (const float*)e4;
            float x0 = x[2 * r], x1 = x[2 * r + 1];
            float p = pangle(x0, x1);
            int q = min(max((int)((p + 1.0f) * (NBUCKET / 4.0f)), 0), NBUCKET - 1);
            int en = sBkt[q];
            int s;
            if (en >= 0) s = en;
            else {
                int c = -en - 1;
                while (sBound[c] <= p) c++;
                s = (c == 0) ? 127 : c - 1;
            }
            const u64* A = &sA64[s * 5];
            float A0, A1, A2, A3, A4, A5, A6, A7;
            upk2(A0, A1, A[0]); upk2(A2, A3, A[1]);
            upk2(A4, A5, A[2]); upk2(A6, A7, A[3]);
            float mu0 = fmaf(A0, x0, fmaf(A1, x1, B20));
            float mu1 = fmaf(A2, x0, fmaf(A3, x1, B21));
            float f2  = fmaf(A4, x0, fmaf(A5, x1, B22));
            float f3  = fmaf(A6, x0, fmaf(A7, x1, B23));
            float fx0, fx1;
            lsum += row_tail(x0, x1, mu0, mu1, f2, f3,
                             y[2 * r], y[2 * r + 1], e[2 * r], e[2 * r + 1],
                             wv00, wv01, wv10, wv11, fx0, fx1);
            ((float*)o4)[2 * r] = fx0;
            ((float*)o4)[2 * r + 1] = fx1;
        }
    } else {
        // general path (b1 != 0): exact scalar MLP per row. Never taken here.
        const float* x = (const float*)x4;
        const float* y = (const float*)y4;
        const float* e = (const float*)e4;
        for (long long r = gtid; r < B; r += gstride) {
            float x0 = x[2 * r], x1 = x[2 * r + 1];
            float f0 = B20, f1 = B21, f2 = B22, f3 = B23;
            for (int j = 0; j < 64; j++) {
                float h = fmaxf(fmaf(x0, sw0[j], fmaf(x1, sw1[j], b1[j])), 0.0f);
                f0 = fmaf(h, sc[j][0], f0);
                f1 = fmaf(h, sc[j][1], f1);
                f2 = fmaf(h, sc[j][2], f2);
                f3 = fmaf(h, sc[j][3], f3);
            }
            float fx0, fx1;
            lsum += row_tail(x0, x1, f0, f1, f2, f3,
                             y[2 * r], y[2 * r + 1], e[2 * r], e[2 * r + 1],
                             wv00, wv01, wv10, wv11, fx0, fx1);
            ((float*)o4)[2 * r] = fx0;
            ((float*)o4)[2 * r + 1] = fx1;
        }
    }

    // reduction: double shuffle within warp, then warp partials, then block
    double dsum = (double)lsum;
#pragma unroll
    for (int off = 16; off; off >>= 1)
        dsum += __shfl_xor_sync(0xffffffffu, dsum, off);
    if ((t & 31) == 0) swred[t >> 5] = dsum;
    __syncthreads();
    if (t < 32) {
        double v = (t < NT / 32) ? swred[t] : 0.0;
#pragma unroll
        for (int off = 8; off; off >>= 1)
            v += __shfl_xor_sync(0xffffffffu, v, off);
        if (t == 0) g_part[blockIdx.x] = v;
    }

    // last-block finalize
    __shared__ bool is_last;
    __threadfence();
    if (t == 0) {
        unsigned prev = atomicAdd(&g_ticket, 1u);
        is_last = (prev == gridDim.x - 1);
    }
    __syncthreads();
    if (is_last) {
        double v = 0.0;
        for (int i = t; i < gridDim.x; i += NT) v += g_part[i];
#pragma unroll
        for (int off = 16; off; off >>= 1)
            v += __shfl_xor_sync(0xffffffffu, v, off);
        if ((t & 31) == 0) swred[t >> 5] = v;
        __syncthreads();
        if (t < 32) {
            double w = (t < NT / 32) ? swred[t] : 0.0;
#pragma unroll
            for (int off = 8; off; off >>= 1)
                w += __shfl_xor_sync(0xffffffffu, w, off);
            if (t == 0) {
                out[2 * B] = (float)(0.5 * w + (double)B * 1.8378770664093453);
                g_ticket = 0;   // reset for next graph replay
            }
        }
    }
}

extern "C" void kernel_launch(void* const* d_in, const int* in_sizes, int n_in,
                              void* d_out, int out_size)
{
    const float* x  = (const float*)d_in[0];
    const float* y  = (const float*)d_in[1];
    const float* e  = (const float*)d_in[2];
    const float* W1 = (const float*)d_in[3];
    const float* b1 = (const float*)d_in[4];
    const float* W2 = (const float*)d_in[5];
    const float* b2 = (const float*)d_in[6];
    const float* Wv = (const float*)d_in[7];
    float* out = (float*)d_out;

    long long B = (long long)in_sizes[0] / 2;
    int nPair = (int)(B / 2);

    int blocks = 304;                    // persistent, 2 blocks/SM
    if (blocks > MAXBLK) blocks = MAXBLK;

    mdn_fused<<<blocks, NT>>>((const float4*)x, (const float4*)y,
                              (const float4*)e, W1, b1, W2, b2, Wv,
                              (float4*)out, out, nPair, B);
}